// round 17
// baseline (speedup 1.0000x reference)
#include <cuda_runtime.h>
#include <math_constants.h>

#define N_NODES 100000
#define N_EDGES 3200000
#define ED 128          // embed dim
#define NG 128          // num graphs
#define NC 10           // num classes
#define NB 129          // buckets = thresholds + 1
#define NHIST (NG * NB) // 16512
#define NSM 148         // persistent grid
#define NTHR 1024

typedef unsigned long long u64;

// Scratch (device globals; zero-init at module load).
// Invariants maintained by every kernel_launch call:
//   g_sd   : zero on entry (re-zeroed in bucket phase)
//   g_hist : zero on entry (re-zeroed by k_final)
//   g_cnt  : zero on entry (re-zeroed by k_final)
//   g_bar  : zero on entry (re-zeroed by k_final)
__device__ float    g_sd[N_NODES];      // edge-sum delta of s
__device__ unsigned g_e[N_NODES];       // enc16 (fixed-point s, scale 256) <<8 | bucket
__device__ u64      g_hist[NHIST];      // global packed hist {sum_enc16<<24 | count}
__device__ int      g_cnt[NG];          // nodes per graph
__device__ float    g_T[ED];            // sorted thresholds
__device__ int      g_rank[ED];         // sorted position of threshold d
__device__ int      g_side[ED];         // 1: active = s > t (suffix); 0: prefix
__device__ int      g_bound[NG + 1];    // graph boundary table (gids sorted)
__device__ int      g_bar;              // grid barrier counter

#define FP_SCALE 256.0f                  // enc16 scale (step 1/256)
#define FP_BIAS  128.0f
#define FP_BIAS_FIX 32768LL              // Σenc16 = 256*ΣS + 32768*cnt

// All 148 CTAs are wave-1 resident (grid == SM count, 1 CTA/SM forced via
// smem), so this counter-spin barrier cannot deadlock. Counter is monotonic
// within a launch; k_final (strictly ordered after) resets it to 0.
// Spin uses a volatile read + nanosleep to avoid hammering the L2 atomic slice.
__device__ __forceinline__ void grid_barrier(int target) {
    __syncthreads();
    __threadfence();
    if (threadIdx.x == 0) {
        atomicAdd(&g_bar, 1);
        volatile int* p = &g_bar;
        while (*p < target) { __nanosleep(64); }
        __threadfence();
    }
    __syncthreads();
}

// ---------------------------------------------------------------------------
// Fused kernel: prep + edges1 + bucket + edges2 (2 internal grid barriers).
__global__ __launch_bounds__(NTHR, 1) void k_fused(const int4* __restrict__ src4,
                                                   const int4* __restrict__ dst4,
                                                   const float* __restrict__ feat,
                                                   const int* __restrict__ gids,
                                                   const float* __restrict__ W1,
                                                   const float* __restrict__ b1) {
    extern __shared__ unsigned sh[];
    unsigned* hist = sh;                  // NHIST u32
    int* bnd = (int*)(sh + NHIST);        // NG+1
    float* T = (float*)(bnd + NG + 1);    // ED
    int* hcnt = (int*)(T + ED);           // NG
    int tid = threadIdx.x;
    int bid = blockIdx.x;
    int gtid = bid * NTHR + tid;
    const int GSTRIDE = NSM * NTHR;       // 151552

    // ---- phase 0a: zero smem hist/hcnt; CTA0/1 do prep ----
    for (int i = tid; i < NHIST; i += NTHR) hist[i] = 0u;
    if (tid < NG) hcnt[tid] = 0;
    if (bid == 0) {
        // thresholds/rank/side (T used as scratch for unsorted ts; it is
        // re-loaded from sorted g_T after barrier 1 by every CTA)
        if (tid < ED) {
            float w = W1[tid], b = b1[tid];
            float t; int side;
            if (w > 0.f)      { t = -b / w; side = 1; }
            else if (w < 0.f) { t = -b / w; side = 0; }
            else              { side = 1; t = (b > 0.f) ? -CUDART_INF_F : CUDART_INF_F; }
            T[tid] = t;
            g_side[tid] = side;
        }
        __syncthreads();
        if (tid < ED) {
            float t = T[tid];
            int r = 0;
#pragma unroll 8
            for (int j = 0; j < ED; j++) {
                float tj = T[j];
                r += (tj < t) || (tj == t && j < tid);
            }
            g_rank[tid] = r;
            g_T[r] = t;
        }
    } else if (bid == 1) {
        // bound[g] = first node index with gids >= g
        if (tid <= NG) {
            int g = tid;
            int lo = 0, hi = N_NODES;
            while (lo < hi) {
                int mid = (lo + hi) >> 1;
                if (__ldg(&gids[mid]) < g) lo = mid + 1; else hi = mid;
            }
            g_bound[g] = lo;
        }
    }

    // ---- phase 0b: edges1 — g_sd[dst] += feat[src], 8 edges/iter ----
    {
        const int half_n = N_EDGES / 8;   // 400000
        for (int i = gtid; i < half_n; i += GSTRIDE) {
            int4 sa = __ldg(&src4[i]);
            int4 ta = __ldg(&dst4[i]);
            int4 sb = __ldg(&src4[i + half_n]);
            int4 tb = __ldg(&dst4[i + half_n]);
            float f0 = __ldg(&feat[sa.x]);
            float f1 = __ldg(&feat[sa.y]);
            float f2 = __ldg(&feat[sa.z]);
            float f3 = __ldg(&feat[sa.w]);
            float f4 = __ldg(&feat[sb.x]);
            float f5 = __ldg(&feat[sb.y]);
            float f6 = __ldg(&feat[sb.z]);
            float f7 = __ldg(&feat[sb.w]);
            atomicAdd(&g_sd[ta.x], f0);
            atomicAdd(&g_sd[ta.y], f1);
            atomicAdd(&g_sd[ta.z], f2);
            atomicAdd(&g_sd[ta.w], f3);
            atomicAdd(&g_sd[tb.x], f4);
            atomicAdd(&g_sd[tb.y], f5);
            atomicAdd(&g_sd[tb.z], f6);
            atomicAdd(&g_sd[tb.w], f7);
        }
    }
    grid_barrier(NSM);

    // ---- phase 1: bucket — s, bucket search, encode, self term into smem ----
    if (tid < ED) T[tid] = g_T[tid];
    if (tid <= NG) bnd[tid] = g_bound[tid];
    __syncthreads();
    for (int n = gtid; n < N_NODES; n += GSTRIDE) {
        float s = feat[n] + g_sd[n];
        g_sd[n] = 0.0f;                   // restore zero invariant
        int b = 0;
#pragma unroll
        for (int st = 128; st > 0; st >>= 1) {
            int nb = b + st;
            if (nb <= ED && T[nb - 1] <= s) b = nb;
        }
        float sc = fminf(fmaxf(s, -FP_BIAS + 1.0f), FP_BIAS - 1.0f);
        unsigned enc = (unsigned)__float2int_rn((sc + FP_BIAS) * FP_SCALE);  // < 2^16
        g_e[n] = (enc << 8) | (unsigned)b;
        int g = gids[n];
        atomicAdd(&hist[g * NB + b], (enc << 8) | 1u);
        atomicAdd(&hcnt[g], 1);
    }
    grid_barrier(2 * NSM);

    // ---- phase 2: edges2 — gather g_e[src], LDS walk for gid(dst), smem add ----
    {
        const int half_n = N_EDGES / 8;   // 400000
#define EOP(e, t) {                                                    \
        int tt = (t);                                                  \
        int gg = (tt * NG) / N_NODES;                                  \
        while (bnd[gg + 1] <= tt) gg++;                                \
        while (bnd[gg] > tt) gg--;                                     \
        atomicAdd(&hist[gg * NB + (int)((e) & 0xFFu)],                 \
                  ((e) & 0xFFFFFF00u) | 1u);                           \
    }
        for (int i = gtid; i < half_n; i += GSTRIDE) {
            int4 sa = __ldg(&src4[i]);
            int4 ta = __ldg(&dst4[i]);
            int4 sb = __ldg(&src4[i + half_n]);
            int4 tb = __ldg(&dst4[i + half_n]);
            unsigned e0 = __ldg(&g_e[sa.x]);
            unsigned e1 = __ldg(&g_e[sa.y]);
            unsigned e2 = __ldg(&g_e[sa.z]);
            unsigned e3 = __ldg(&g_e[sa.w]);
            unsigned e4 = __ldg(&g_e[sb.x]);
            unsigned e5 = __ldg(&g_e[sb.y]);
            unsigned e6 = __ldg(&g_e[sb.z]);
            unsigned e7 = __ldg(&g_e[sb.w]);
            EOP(e0, ta.x);
            EOP(e1, ta.y);
            EOP(e2, ta.z);
            EOP(e3, ta.w);
            EOP(e4, tb.x);
            EOP(e5, tb.y);
            EOP(e6, tb.z);
            EOP(e7, tb.w);
        }
#undef EOP
    }
    __syncthreads();
    // flush nonzero entries, widening {sum:24|cnt:8} -> global {sum:40|cnt:24}
    for (int i = tid; i < NHIST; i += NTHR) {
        unsigned v = hist[i];
        if (v) atomicAdd(&g_hist[i], ((u64)(v >> 8) << 24) | (u64)(v & 0xFFu));
    }
    if (tid < NG && hcnt[tid]) atomicAdd(&g_cnt[tid], hcnt[tid]);
}

// ---------------------------------------------------------------------------
// K4: per graph — read + rezero g_hist/g_cnt, reset barrier, suffix sums,
//     reconstruct hg, 3-layer head.
__global__ __launch_bounds__(128) void k_final(const float* __restrict__ W1,
                                               const float* __restrict__ b1,
                                               const float* __restrict__ W2,
                                               const float* __restrict__ b2,
                                               const float* __restrict__ Wf1,
                                               const float* __restrict__ bf1,
                                               const float* __restrict__ Wf2,
                                               const float* __restrict__ bf2,
                                               float* __restrict__ out) {
    __shared__ float bs[NB], bc[NB];
    __shared__ float suffS[NB + 1], suffC[NB + 1];
    __shared__ float a_sh[ED], h_sh[ED];
    __shared__ float invc_sh;
    int g = blockIdx.x;
    int d = threadIdx.x;

    if (g == 0 && d == 0) atomicExch(&g_bar, 0);   // reset barrier for next run
    if (d == 0) {
        int c = g_cnt[g];
        g_cnt[g] = 0;                          // restore zero invariant
        invc_sh = 1.0f / fmaxf((float)c, 1.0f);
    }
    for (int idx = d; idx < NB; idx += ED) {
        int off = g * NB + idx;
        u64 h = g_hist[off];
        g_hist[off] = 0ull;                    // restore zero invariant
        long long cnt = (long long)(h & 0xFFFFFFull);
        long long sumq = (long long)(h >> 24);            // Σ enc16
        long long sfix = sumq - cnt * FP_BIAS_FIX;        // 256 * ΣS
        bs[idx] = (float)sfix * (1.0f / FP_SCALE);
        bc[idx] = (float)cnt;
    }
    __syncthreads();
    if (d == 0) {
        double as = 0.0, ac = 0.0;
        suffS[NB] = 0.f; suffC[NB] = 0.f;
        for (int k = NB - 1; k >= 0; k--) {
            as += (double)bs[k]; ac += (double)bc[k];
            suffS[k] = (float)as; suffC[k] = (float)ac;
        }
    }
    __syncthreads();

    // hg[g,d] = (W1[d]*S_active + b1[d]*C_active) / count[g]
    {
        float w = W1[d], b = b1[d];
        int r = g_rank[d];
        float S = suffS[r + 1], C = suffC[r + 1];
        if (!g_side[d]) { S = suffS[0] - S; C = suffC[0] - C; }
        a_sh[d] = (w * S + b * C) * invc_sh;
    }
    __syncthreads();

    float acc = b2[d];
#pragma unroll 8
    for (int k = 0; k < ED; k++) acc = fmaf(a_sh[k], W2[k * ED + d], acc);
    h_sh[d] = acc;
    __syncthreads();

    acc = bf1[d];
#pragma unroll 8
    for (int k = 0; k < ED; k++) acc = fmaf(h_sh[k], Wf1[k * ED + d], acc);
    acc = fmaxf(acc, 0.0f);
    __syncthreads();
    a_sh[d] = acc;
    __syncthreads();

    if (d < NC) {
        float o = bf2[d];
#pragma unroll 8
        for (int k = 0; k < ED; k++) o = fmaf(a_sh[k], Wf2[k * NC + d], o);
        out[g * NC + d] = o;
    }
}

// ---------------------------------------------------------------------------
extern "C" void kernel_launch(void* const* d_in, const int* in_sizes, int n_in,
                              void* d_out, int out_size) {
    const float* feat = (const float*)d_in[0];
    const int*   src  = (const int*)d_in[1];
    const int*   dst  = (const int*)d_in[2];
    const int*   gids = (const int*)d_in[3];
    const float* W1   = (const float*)d_in[4];
    const float* b1   = (const float*)d_in[5];
    const float* W2   = (const float*)d_in[6];
    const float* b2   = (const float*)d_in[7];
    const float* Wf1  = (const float*)d_in[8];
    const float* bf1  = (const float*)d_in[9];
    const float* Wf2  = (const float*)d_in[10];
    const float* bf2  = (const float*)d_in[11];
    float* out = (float*)d_out;

    // Force 1 CTA/SM (smem > half of 227KB) so all 148 CTAs are wave-1
    // resident and the spin barrier cannot deadlock.
    const int smem_fused = 120 * 1024;
    static bool attr_done = false;
    if (!attr_done) {
        cudaFuncSetAttribute(k_fused, cudaFuncAttributeMaxDynamicSharedMemorySize, smem_fused);
        attr_done = true;
    }

    k_fused<<<NSM, NTHR, smem_fused>>>((const int4*)src, (const int4*)dst,
                                       feat, gids, W1, b1);
    k_final<<<NG, ED>>>(W1, b1, W2, b2, Wf1, bf1, Wf2, bf2, out);
}